// round 5
// baseline (speedup 1.0000x reference)
#include <cuda_runtime.h>

#define NUM_CLS   8
#define MAX_INST  64
#define NB        32            // batch
#define HW        (1024*1024)   // pixels per sample
#define HT        256           // threads per hist block
#define CHUNKS    32            // blocks per sample along pixel dim

// Per-block histogram partials, written with plain stores (no zeroing needed).
__device__ int g_part[NB * CHUNKS * MAX_INST];   // 256 KB

// ---------------- kernel 1: per-sample 64-bin histogram ----------------
// Privatized per-thread u16 counters: cnt[bin*HT + tid]. bank = f(tid) ->
// conflict-free LDS/STS regardless of bin. Max 128 elems/thread -> no overflow.
__global__ __launch_bounds__(HT) void hist_kernel(const int* __restrict__ mask) {
    __shared__ unsigned short cnt[MAX_INST * HT];   // 32 KB (psum reuses tail)

    const int tid = threadIdx.x;
    unsigned int* cnt32 = (unsigned int*)cnt;

    #pragma unroll
    for (int i = tid; i < MAX_INST * HT / 2; i += HT) cnt32[i] = 0u;
    __syncthreads();

    const int sample = blockIdx.y;
    const int chunk  = blockIdx.x;
    const int elems  = HW / CHUNKS;     // 32768 per block

    const int4* __restrict__ p =
        (const int4*)(mask + (size_t)sample * HW + (size_t)chunk * elems) + tid;

#define INC(v) cnt[((v) & 63) * HT + tid]++

    // 32 int4/thread = 4 outer iters of 8 explicitly-batched independent loads
    #pragma unroll 1
    for (int it = 0; it < 4; it++) {
        int4 a = p[0 * HT];
        int4 b = p[1 * HT];
        int4 c = p[2 * HT];
        int4 d = p[3 * HT];
        int4 e = p[4 * HT];
        int4 f = p[5 * HT];
        int4 g = p[6 * HT];
        int4 h = p[7 * HT];
        p += 8 * HT;
        INC(a.x); INC(a.y); INC(a.z); INC(a.w);
        INC(b.x); INC(b.y); INC(b.z); INC(b.w);
        INC(c.x); INC(c.y); INC(c.z); INC(c.w);
        INC(d.x); INC(d.y); INC(d.z); INC(d.w);
        INC(e.x); INC(e.y); INC(e.z); INC(e.w);
        INC(f.x); INC(f.y); INC(f.z); INC(f.w);
        INC(g.x); INC(g.y); INC(g.z); INC(g.w);
        INC(h.x); INC(h.y); INC(h.z); INC(h.w);
    }
#undef INC
    __syncthreads();

    // Reduce 256 u16 lanes per bin. 4 threads per bin (j = tid>>6), each sums
    // 32 packed words with a tid-stagger -> conflict-free LDS.
    unsigned int s = 0;
    {
        const int b = tid & 63;
        const int j = tid >> 6;
        #pragma unroll
        for (int i = 0; i < 32; i++) {
            unsigned int w = cnt32[b * (HT / 2) + j * 32 + ((i + tid) & 31)];
            s += (w & 0xffffu) + (w >> 16);
        }
    }
    __syncthreads();                      // counters no longer needed
    unsigned int* psum = cnt32;           // reuse smem
    psum[tid] = s;
    __syncthreads();
    if (tid < MAX_INST) {
        unsigned int t = psum[tid] + psum[tid + 64] + psum[tid + 128] + psum[tid + 192];
        g_part[(sample * CHUNKS + chunk) * MAX_INST + tid] = (int)t;
    }
}

// ---------------- kernel 2: partial-sum + gather/scatter + BCE loss ----------------
__global__ __launch_bounds__(256) void loss_kernel(const float* __restrict__ pred,
                                                   const int*   __restrict__ label_raw,
                                                   float* __restrict__ out) {
    __shared__ int   isz[NB * MAX_INST];
    __shared__ int   cnts[NB * NUM_CLS];
    __shared__ float red[8];
    __shared__ int   s_notzero;

    const int tid = threadIdx.x;

    if (tid == 0) s_notzero = 0;
    if (tid < NB * NUM_CLS) cnts[tid] = 0;

    // Sum histogram partials over chunks; int4 over contiguous bin dim.
    // 2048 sums -> 512 int4 work items -> 2 per thread, 32 c-iters each.
    for (int w = tid; w < NB * MAX_INST / 4; w += 256) {
        int s = w >> 4;            // sample (16 int4 groups per sample)
        int b4 = w & 15;           // which group of 4 bins
        int4 acc = make_int4(0, 0, 0, 0);
        const int4* gp = (const int4*)g_part + (size_t)s * CHUNKS * 16 + b4;
        #pragma unroll
        for (int c = 0; c < CHUNKS; c++) {
            int4 v = gp[c * 16];
            acc.x += v.x; acc.y += v.y; acc.z += v.z; acc.w += v.w;
        }
        ((int4*)isz)[w] = acc;
    }

    // Parallel int64-vs-int32 detection: values < 32, so for little-endian
    // int64 every odd 32-bit word (high half) of the first 64 values is 0.
    if (tid < 64) {
        if (label_raw[2 * tid + 1] != 0) atomicOr(&s_notzero, 1);
    }
    __syncthreads();

    const int is64 = !s_notzero;
    for (int p = tid; p < NB * 64; p += 256) {
        int b = p >> 6;
        int id, lbl;
        if (is64) { id = label_raw[4 * p]; lbl = label_raw[4 * p + 2]; }
        else      { id = label_raw[2 * p]; lbl = label_raw[2 * p + 1]; }
        if (lbl > 0 && lbl <= NUM_CLS)
            atomicAdd(&cnts[b * NUM_CLS + lbl - 1], isz[b * MAX_INST + (id & (MAX_INST - 1))]);
    }
    __syncthreads();

    float term = 0.0f;
    if (tid < NB * NUM_CLS) {
        float x  = pred[tid];
        float cl = fminf((float)cnts[tid] * (1.0f / 100.0f), 1.0f);
        term = fmaxf(x, 0.0f) - x * cl + log1pf(expf(-fabsf(x)));
    }
    #pragma unroll
    for (int o = 16; o; o >>= 1) term += __shfl_down_sync(0xffffffffu, term, o);
    if ((tid & 31) == 0) red[tid >> 5] = term;
    __syncthreads();
    if (tid < 8) {
        float s = red[tid];
        #pragma unroll
        for (int o = 4; o; o >>= 1) s += __shfl_down_sync(0xffu, s, o);
        if (tid == 0) out[0] = s * (1.0f / (float)(NB * NUM_CLS));
    }
}

// ---------------- launch ----------------
extern "C" void kernel_launch(void* const* d_in, const int* in_sizes, int n_in,
                              void* d_out, int out_size) {
    const float* pred  = (const float*)d_in[0];          // [32, 8] f32
    const int*   mask  = (const int*)d_in[1];            // [32, 1024, 1024] i32
    const int*   label = (const int*)d_in[2];            // [32, 64, 2] i32 or i64
    float*       out   = (float*)d_out;

    dim3 grid(CHUNKS, NB);
    hist_kernel<<<grid, HT>>>(mask);
    loss_kernel<<<1, 256>>>(pred, label, out);
}

// round 7
// speedup vs baseline: 1.1098x; 1.1098x over previous
#include <cuda_runtime.h>

#define NUM_CLS   8
#define MAX_INST  64
#define NB        32            // batch
#define HW        (1024*1024)   // pixels per sample
#define HT        256           // threads per block
#define CHUNKS    32            // blocks per sample along pixel dim
#define GRID      (NB * CHUNKS) // 1024 blocks ~= one wave at 7 blocks/SM

__device__ __align__(16) int g_inst_sizes[NB * MAX_INST];  // static-zero; reset each run
__device__ unsigned int g_done;                            // static-zero; reset each run

// One fused kernel: per-block 64-bin histogram (privatized u16 counters),
// global accumulation via atomics, last-block-done computes the BCE loss.
__global__ __launch_bounds__(HT, 7) void fused_kernel(const int*   __restrict__ mask,
                                                      const float* __restrict__ pred,
                                                      const int*   __restrict__ label_raw,
                                                      float*       __restrict__ out) {
    __shared__ __align__(16) unsigned short cnt[MAX_INST * HT];  // 32 KB, reused in tail
    __shared__ unsigned int s_ticket;

    const int tid = threadIdx.x;
    unsigned int* cnt32 = (unsigned int*)cnt;

    #pragma unroll
    for (int i = tid; i < MAX_INST * HT / 2; i += HT) cnt32[i] = 0u;
    __syncthreads();

    const int sample = blockIdx.y;
    const int chunk  = blockIdx.x;
    const int elems  = HW / CHUNKS;     // 32768 per block

    const int4* __restrict__ p =
        (const int4*)(mask + (size_t)sample * HW + (size_t)chunk * elems) + tid;

#define INC(v) cnt[((v) & 63) * HT + tid]++
    // 32 int4/thread: 8 iters of 4 explicitly-batched independent loads (MLP=4,
    // 16 load regs -> occupancy stays smem-limited at 7 blocks/SM).
    #pragma unroll 2
    for (int it = 0; it < 8; it++) {
        int4 a = p[0 * HT];
        int4 b = p[1 * HT];
        int4 c = p[2 * HT];
        int4 d = p[3 * HT];
        p += 4 * HT;
        INC(a.x); INC(a.y); INC(a.z); INC(a.w);
        INC(b.x); INC(b.y); INC(b.z); INC(b.w);
        INC(c.x); INC(c.y); INC(c.z); INC(c.w);
        INC(d.x); INC(d.y); INC(d.z); INC(d.w);
    }
#undef INC
    __syncthreads();

    // Reduce 256 u16 lanes per bin: 4 threads/bin, tid-staggered -> conflict-free.
    unsigned int s = 0;
    {
        const int b = tid & 63;
        const int j = tid >> 6;
        #pragma unroll
        for (int i = 0; i < 32; i++) {
            unsigned int w = cnt32[b * (HT / 2) + j * 32 + ((i + tid) & 31)];
            s += (w & 0xffffu) + (w >> 16);
        }
    }
    __syncthreads();
    unsigned int* psum = cnt32;           // reuse smem
    psum[tid] = s;
    __syncthreads();
    if (tid < MAX_INST) {
        unsigned int t = psum[tid] + psum[tid + 64] + psum[tid + 128] + psum[tid + 192];
        atomicAdd(&g_inst_sizes[sample * MAX_INST + tid], (int)t);
    }

    // ---- last-block-done handoff ----
    __threadfence();                       // bin atomics visible before ticket
    __syncthreads();
    if (tid == 0) s_ticket = atomicAdd(&g_done, 1u);
    __syncthreads();
    if (s_ticket != GRID - 1) return;      // uniform exit for non-last blocks

    // ================= last block: loss computation =================
    __threadfence();                       // acquire: see all blocks' bin atomics

    int*   isz   = (int*)cnt32;            // [2048] totals (8 KB)
    int*   cnts  = isz + NB * MAX_INST;    // [256] per-class pixel counts
    float* red   = (float*)(cnts + NB * NUM_CLS);
    int*   flags = (int*)(red + 8);

    for (int i = tid; i < NB * MAX_INST / 4; i += HT)
        ((int4*)isz)[i] = ((const int4*)g_inst_sizes)[i];     // L2-hot, 8 KB
    if (tid == 0) flags[0] = 0;
    if (tid < NB * NUM_CLS) cnts[tid] = 0;
    __syncthreads();

    // Reset globals for the next graph replay (after totals are in shared).
    for (int i = tid; i < NB * MAX_INST / 4; i += HT)
        ((int4*)g_inst_sizes)[i] = make_int4(0, 0, 0, 0);
    if (tid == 0) g_done = 0u;

    // int64-vs-int32 layout detection: values < 32, so little-endian int64
    // means every odd 32-bit word of the first 64 values is 0.
    if (tid < 64) {
        if (label_raw[2 * tid + 1] != 0) atomicOr(&flags[0], 1);
    }
    __syncthreads();

    const int is64 = !flags[0];
    for (int q = tid; q < NB * 64; q += HT) {
        int b = q >> 6;
        int id, lbl;
        if (is64) { id = label_raw[4 * q]; lbl = label_raw[4 * q + 2]; }
        else      { id = label_raw[2 * q]; lbl = label_raw[2 * q + 1]; }
        if (lbl > 0 && lbl <= NUM_CLS)
            atomicAdd(&cnts[b * NUM_CLS + lbl - 1], isz[b * MAX_INST + (id & (MAX_INST - 1))]);
    }
    __syncthreads();

    float term = 0.0f;
    if (tid < NB * NUM_CLS) {
        float x  = pred[tid];
        float cl = fminf((float)cnts[tid] * (1.0f / 100.0f), 1.0f);
        term = fmaxf(x, 0.0f) - x * cl + log1pf(expf(-fabsf(x)));
    }
    #pragma unroll
    for (int o = 16; o; o >>= 1) term += __shfl_down_sync(0xffffffffu, term, o);
    if ((tid & 31) == 0) red[tid >> 5] = term;
    __syncthreads();
    if (tid < 8) {
        float sr = red[tid];
        #pragma unroll
        for (int o = 4; o; o >>= 1) sr += __shfl_down_sync(0xffu, sr, o);
        if (tid == 0) out[0] = sr * (1.0f / (float)(NB * NUM_CLS));
    }
}

// ---------------- launch ----------------
extern "C" void kernel_launch(void* const* d_in, const int* in_sizes, int n_in,
                              void* d_out, int out_size) {
    const float* pred  = (const float*)d_in[0];          // [32, 8] f32
    const int*   mask  = (const int*)d_in[1];            // [32, 1024, 1024] i32
    const int*   label = (const int*)d_in[2];            // [32, 64, 2] i32 or i64
    float*       out   = (float*)d_out;

    dim3 grid(CHUNKS, NB);
    fused_kernel<<<grid, HT>>>(mask, pred, label, out);
}